// round 11
// baseline (speedup 1.0000x reference)
#include <cuda_runtime.h>

// Problem constants
#define KK 64
#define CC 16
#define NRAYS 131072           // N*R = 2*65536
#define KM1 63

// Output layout: tuple flattened in order
#define OFF_CC 0
#define OFF_RD (NRAYS*CC)              // 2,097,152
#define OFF_W  (OFF_RD + NRAYS)        // 2,228,224
#define OFF_TE (OFF_W + NRAYS*KM1)     // 10,485,760

// Global max of radii midpoints, as ordered int bits (all values positive).
__device__ int g_max_bits;

// ---------------------------------------------------------------------------
// Kernel 0: reset the atomic target (runs every replay — deterministic).
// ---------------------------------------------------------------------------
__global__ void init_kernel() { g_max_bits = 0; }

// ---------------------------------------------------------------------------
// Kernel 1: main compositing — ONE WARP PER RAY, no block barriers, no smem.
// Lane L holds elements L and L+32 of the ray's r/d arrays (coalesced loads).
// T computed by warp-wide multiplicative inclusive scan of f = exp(-x)+eps.
// Colors streamed as 8 x LDG.128 per lane; u[j]=w[j-1]+w[j] gathered via
// dynamic-index shfl. Per-warp REDG atomicMax accumulates the global max
// midpoint (lane 30's rmB = midpoint k=62; radii sorted => ray max).
// ---------------------------------------------------------------------------
__global__ __launch_bounds__(256, 6)
void composite_kernel(const float* __restrict__ colors,
                      const float* __restrict__ densities,
                      const float* __restrict__ radii,
                      float* __restrict__ out) {
    const unsigned FULL = 0xffffffffu;
    const int L = threadIdx.x & 31;
    const int wi = threadIdx.x >> 5;
    const int ray = blockIdx.x * 8 + wi;
    const size_t base = (size_t)ray * KK;

    // ---- coalesced loads: lane L gets elements L and L+32 -----------------
    float rA = __ldg(radii + base + L);
    float rB = __ldg(radii + base + 32 + L);
    float dA = __ldg(densities + base + L);
    float dB = __ldg(densities + base + 32 + L);

    // ---- neighbors for midpoints/deltas -----------------------------------
    float rA1 = __shfl_down_sync(FULL, rA, 1);
    float dA1 = __shfl_down_sync(FULL, dA, 1);
    float rB0 = __shfl_sync(FULL, rB, 0);
    float dB0 = __shfl_sync(FULL, dB, 0);
    if (L == 31) { rA1 = rB0; dA1 = dB0; }       // element 32
    float rB1 = __shfl_down_sync(FULL, rB, 1);   // lane31: self (padded out)
    float dB1 = __shfl_down_sync(FULL, dB, 1);

    // ---- per-interval quantities: k=L (A) and k=L+32 (B), k<=62 -----------
    float xA = (rA1 - rA) * fmaxf(0.5f * (dA + dA1), 0.0f);
    float xB = (rB1 - rB) * fmaxf(0.5f * (dB + dB1), 0.0f);
    float rmA = 0.5f * (rA + rA1);
    float rmB = 0.5f * (rB + rB1);
    float eA = __expf(-xA);
    float eB = (L == 31) ? 1.0f : __expf(-xB);   // k=63 pad: alpha=0
    float fA = eA + 1e-10f;
    float fB = (L == 31) ? 1.0f : (eB + 1e-10f);

    // global max midpoint: lane 30 holds rm[62] (ray max, radii sorted)
    if (L == 30) atomicMax(&g_max_bits, __float_as_int(rmB));

    // ---- warp-wide multiplicative inclusive scan of f ----------------------
    float FA = fA;
    #pragma unroll
    for (int o = 1; o < 32; o <<= 1) {
        float t = __shfl_up_sync(FULL, FA, o);
        if (L >= o) FA *= t;
    }
    float tot = __shfl_sync(FULL, FA, 31);       // prod f[0..31]
    float FB = fB;
    #pragma unroll
    for (int o = 1; o < 32; o <<= 1) {
        float t = __shfl_up_sync(FULL, FB, o);
        if (L >= o) FB *= t;
    }
    FB *= tot;                                   // inclusive over 0..L+32

    // ---- transmittance T_k = F_{k-1} --------------------------------------
    float tA = __shfl_up_sync(FULL, FA, 1);
    float TA = (L == 0) ? 1.0f : tA;             // k = L
    float tB = __shfl_up_sync(FULL, FB, 1);
    float TB = (L == 0) ? tot : tB;              // k = L+32

    // ---- weights ----------------------------------------------------------
    float wA = (1.0f - eA) * TA;                 // k = 0..31
    float wB = (1.0f - eB) * TB;                 // k = 32..62 (lane31 -> 0)

    // weights output: row of 63 floats, two coalesced stores
    float* wout = out + OFF_W + (size_t)ray * KM1;
    wout[L] = wA;
    if (L < 31) wout[32 + L] = wB;

    // ---- u[j] = w[j-1] + w[j]  (u[0]=w0, u[63]=w62) -----------------------
    float pA = __shfl_up_sync(FULL, wA, 1);
    float uA = wA + ((L == 0) ? 0.0f : pA);
    float wA31 = __shfl_sync(FULL, wA, 31);
    float pB = __shfl_up_sync(FULL, wB, 1);
    float uB = wB + ((L == 0) ? wA31 : pB);

    // ---- per-ray scalar outputs -------------------------------------------
    float ws = wA + wB;
    float rs = wA * rmA + wB * rmB;
    #pragma unroll
    for (int o = 16; o > 0; o >>= 1) {
        ws += __shfl_xor_sync(FULL, ws, o);
        rs += __shfl_xor_sync(FULL, rs, o);
    }
    float tend = __shfl_sync(FULL, TB, 30);      // T[62]
    if (L == 0) {
        out[OFF_RD + ray] = rs / ws;             // unclipped; fixup clips
        out[OFF_TE + ray] = tend;
    }

    // ---- color streaming: 8 x LDG.128 per lane ----------------------------
    // lane L consumes samples k = (L>>2) + 8i; u[k] gathered via shfl.idx
    const float4* cp = (const float4*)(colors + base * CC);
    const int j0 = L >> 2;
    float4 acc = make_float4(0.0f, 0.0f, 0.0f, 0.0f);
    #pragma unroll
    for (int i = 0; i < 8; i++) {
        float4 cv = __ldg(cp + i * 32 + L);
        int src = j0 + 8 * (i & 3);
        float u = (i < 4) ? __shfl_sync(FULL, uA, src)
                          : __shfl_sync(FULL, uB, src);
        acc.x += cv.x * u;
        acc.y += cv.y * u;
        acc.z += cv.z * u;
        acc.w += cv.w * u;
    }
    // reduce over the 8 sample-classes (lanes differing in bits 2..4)
    #pragma unroll
    for (int o = 4; o <= 16; o <<= 1) {
        acc.x += __shfl_xor_sync(FULL, acc.x, o);
        acc.y += __shfl_xor_sync(FULL, acc.y, o);
        acc.z += __shfl_xor_sync(FULL, acc.z, o);
        acc.w += __shfl_xor_sync(FULL, acc.w, o);
    }
    if (L < 4) {
        float4 o4 = make_float4(acc.x - 1.0f, acc.y - 1.0f,
                                acc.z - 1.0f, acc.w - 1.0f);
        *(float4*)(out + OFF_CC + (size_t)ray * CC + L * 4) = o4;
    }
}

// ---------------------------------------------------------------------------
// Kernel 2: clip composite_radial_dist. cr is a convex combination of the
// ray's own midpoints when ws>0 (clip provably a no-op); only nan/inf from
// degenerate rays need fixing: fminf maps both to gmax. Min-clip: cr >= ray
// min midpoint >= global min, also a no-op.
// ---------------------------------------------------------------------------
__global__ void fixup_kernel(float* __restrict__ out) {
    int i = blockIdx.x * blockDim.x + threadIdx.x;
    float gmax = __int_as_float(g_max_bits);
    out[OFF_RD + i] = fminf(out[OFF_RD + i], gmax);   // fminf(nan,x)=x
}

// ---------------------------------------------------------------------------
extern "C" void kernel_launch(void* const* d_in, const int* in_sizes, int n_in,
                              void* d_out, int out_size) {
    const float* colors    = (const float*)d_in[0];
    const float* densities = (const float*)d_in[1];
    const float* radii     = (const float*)d_in[2];
    float* out = (float*)d_out;

    init_kernel<<<1, 1>>>();
    composite_kernel<<<NRAYS / 8, 256>>>(colors, densities, radii, out);
    fixup_kernel<<<NRAYS / 256, 256>>>(out);
}

// round 12
// speedup vs baseline: 2.0528x; 2.0528x over previous
#include <cuda_runtime.h>

// Problem constants
#define KK 64
#define CC 16
#define NRAYS 131072           // N*R = 2*65536
#define KM1 63

// Output layout: tuple flattened in order
#define OFF_CC 0
#define OFF_RD (NRAYS*CC)              // 2,097,152
#define OFF_W  (OFF_RD + NRAYS)        // 2,228,224
#define OFF_TE (OFF_W + NRAYS*KM1)     // 10,485,760

#define NPART 128              // partial maxima (one per maxk block)

// Scratch: fully overwritten every replay — graph-deterministic, no init pass.
__device__ float g_partial[NPART];

// ---------------------------------------------------------------------------
// Kernel 1: per-block max of last radii midpoint. radii sorted along K ⇒
// global max midpoint = max over rays of 0.5*(r62+r63). 4 rays per thread
// (4-way MLP) so the pass is bandwidth/latency-efficient, not launch-bound.
// ---------------------------------------------------------------------------
__global__ __launch_bounds__(256)
void maxk_kernel(const float* __restrict__ radii) {
    float mx = 0.0f;
    #pragma unroll
    for (int i = 0; i < 4; i++) {
        int ray = blockIdx.x * 1024 + i * 256 + threadIdx.x;
        float2 hi = *(const float2*)(radii + (size_t)ray * KK + (KK - 2));
        mx = fmaxf(mx, hi.x + hi.y);            // defer the *0.5
    }
    mx *= 0.5f;
    #pragma unroll
    for (int o = 16; o > 0; o >>= 1)
        mx = fmaxf(mx, __shfl_xor_sync(0xffffffffu, mx, o));
    __shared__ float smx[8];
    if ((threadIdx.x & 31) == 0) smx[threadIdx.x >> 5] = mx;
    __syncthreads();
    if (threadIdx.x == 0) {
        #pragma unroll
        for (int i = 1; i < 8; i++) mx = fmaxf(mx, smx[i]);
        g_partial[blockIdx.x] = mx;
    }
}

// ---------------------------------------------------------------------------
// Kernel 2: main compositing — ONE WARP PER RAY, no block barriers.
// Lane L holds elements L and L+32 of the ray's r/d arrays (coalesced loads).
// T computed by warp-wide multiplicative inclusive scan of f = exp(-x)+eps.
// Colors streamed as 8 x LDG.128 per lane with u[j]=w[j-1]+w[j] coefficients
// staged through shared memory (NOT registers: with the 6-block launch bound
// the reg budget is 40, and keeping u live across the color loop spills).
// Each warp folds the 128 L2-resident partial maxima for the clip bound.
// ---------------------------------------------------------------------------
__global__ __launch_bounds__(256, 6)
void composite_kernel(const float* __restrict__ colors,
                      const float* __restrict__ densities,
                      const float* __restrict__ radii,
                      float* __restrict__ out) {
    __shared__ float s_u[8][64];          // per-warp u coefficients (2 KB)
    const unsigned FULL = 0xffffffffu;
    const int L = threadIdx.x & 31;
    const int wi = threadIdx.x >> 5;
    const int ray = blockIdx.x * 8 + wi;
    const size_t base = (size_t)ray * KK;

    // ---- coalesced loads: lane L gets elements L and L+32 -----------------
    float rA = __ldg(radii + base + L);
    float rB = __ldg(radii + base + 32 + L);
    float dA = __ldg(densities + base + L);
    float dB = __ldg(densities + base + 32 + L);

    // ---- neighbors for midpoints/deltas -----------------------------------
    float rA1 = __shfl_down_sync(FULL, rA, 1);
    float dA1 = __shfl_down_sync(FULL, dA, 1);
    float rB0 = __shfl_sync(FULL, rB, 0);
    float dB0 = __shfl_sync(FULL, dB, 0);
    if (L == 31) { rA1 = rB0; dA1 = dB0; }       // element 32
    float rB1 = __shfl_down_sync(FULL, rB, 1);   // lane31: self (padded out)
    float dB1 = __shfl_down_sync(FULL, dB, 1);

    // ---- per-interval quantities: k=L (A) and k=L+32 (B), k<=62 -----------
    float xA = (rA1 - rA) * fmaxf(0.5f * (dA + dA1), 0.0f);
    float xB = (rB1 - rB) * fmaxf(0.5f * (dB + dB1), 0.0f);
    float rmA = 0.5f * (rA + rA1);
    float rmB = 0.5f * (rB + rB1);
    float eA = __expf(-xA);
    float eB = (L == 31) ? 1.0f : __expf(-xB);   // k=63 pad: alpha=0
    float fA = eA + 1e-10f;
    float fB = (L == 31) ? 1.0f : (eB + 1e-10f);

    // ---- warp-wide multiplicative inclusive scan of f ----------------------
    float FA = fA;
    #pragma unroll
    for (int o = 1; o < 32; o <<= 1) {
        float t = __shfl_up_sync(FULL, FA, o);
        if (L >= o) FA *= t;
    }
    float tot = __shfl_sync(FULL, FA, 31);       // prod f[0..31]
    float FB = fB;
    #pragma unroll
    for (int o = 1; o < 32; o <<= 1) {
        float t = __shfl_up_sync(FULL, FB, o);
        if (L >= o) FB *= t;
    }
    FB *= tot;                                   // inclusive over 0..L+32

    // ---- transmittance T_k = F_{k-1} --------------------------------------
    float tA = __shfl_up_sync(FULL, FA, 1);
    float TA = (L == 0) ? 1.0f : tA;             // k = L
    float tB = __shfl_up_sync(FULL, FB, 1);
    float TB = (L == 0) ? tot : tB;              // k = L+32

    // ---- weights ----------------------------------------------------------
    float wA = (1.0f - eA) * TA;                 // k = 0..31
    float wB = (1.0f - eB) * TB;                 // k = 32..62 (lane31 -> 0)

    // weights output: row of 63 floats, two coalesced stores
    float* wout = out + OFF_W + (size_t)ray * KM1;
    wout[L] = wA;
    if (L < 31) wout[32 + L] = wB;

    // ---- u[j] = w[j-1] + w[j]  (u[0]=w0, u[63]=w62) -----------------------
    float pA = __shfl_up_sync(FULL, wA, 1);
    float uA = wA + ((L == 0) ? 0.0f : pA);
    float wA31 = __shfl_sync(FULL, wA, 31);
    float pB = __shfl_up_sync(FULL, wB, 1);
    float uB = wB + ((L == 0) ? wA31 : pB);
    s_u[wi][L] = uA;
    s_u[wi][32 + L] = uB;

    // ---- per-ray scalar outputs -------------------------------------------
    float ws = wA + wB;
    float rs = wA * rmA + wB * rmB;
    #pragma unroll
    for (int o = 16; o > 0; o >>= 1) {
        ws += __shfl_xor_sync(FULL, ws, o);
        rs += __shfl_xor_sync(FULL, rs, o);
    }
    // fold the 128 partial maxima (L2-resident after first warp)
    float pm = fmaxf(fmaxf(g_partial[L],      g_partial[L + 32]),
                     fmaxf(g_partial[L + 64], g_partial[L + 96]));
    #pragma unroll
    for (int o = 16; o > 0; o >>= 1)
        pm = fmaxf(pm, __shfl_xor_sync(FULL, pm, o));
    float tend = __shfl_sync(FULL, TB, 30);      // T[62]
    if (L == 0) {
        // cr is a convex combination of this ray's midpoints when ws>0 (so
        // the reference clip is a no-op there, incl. the min side); nan/inf
        // and overflow from ws~0 all map to gmax via fminf (fminf(nan,x)=x).
        out[OFF_RD + ray] = fminf(rs / ws, pm);
        out[OFF_TE + ray] = tend;
    }
    __syncwarp();

    // ---- color streaming: 8 x LDG.128 per lane ----------------------------
    const float4* cp = (const float4*)(colors + base * CC);
    const float* su = &s_u[wi][L >> 2];          // sample k0 = L>>2 (+8i)
    float4 acc = make_float4(0.0f, 0.0f, 0.0f, 0.0f);
    #pragma unroll
    for (int i = 0; i < 8; i++) {
        float4 cv = __ldg(cp + i * 32 + L);
        float u = su[i * 8];
        acc.x += cv.x * u;
        acc.y += cv.y * u;
        acc.z += cv.z * u;
        acc.w += cv.w * u;
    }
    // reduce over the 8 sample-classes (lanes differing in bits 2..4)
    #pragma unroll
    for (int o = 4; o <= 16; o <<= 1) {
        acc.x += __shfl_xor_sync(FULL, acc.x, o);
        acc.y += __shfl_xor_sync(FULL, acc.y, o);
        acc.z += __shfl_xor_sync(FULL, acc.z, o);
        acc.w += __shfl_xor_sync(FULL, acc.w, o);
    }
    if (L < 4) {
        float4 o4 = make_float4(acc.x - 1.0f, acc.y - 1.0f,
                                acc.z - 1.0f, acc.w - 1.0f);
        *(float4*)(out + OFF_CC + (size_t)ray * CC + L * 4) = o4;
    }
}

// ---------------------------------------------------------------------------
extern "C" void kernel_launch(void* const* d_in, const int* in_sizes, int n_in,
                              void* d_out, int out_size) {
    const float* colors    = (const float*)d_in[0];
    const float* densities = (const float*)d_in[1];
    const float* radii     = (const float*)d_in[2];
    float* out = (float*)d_out;

    maxk_kernel<<<NPART, 256>>>(radii);
    composite_kernel<<<NRAYS / 8, 256>>>(colors, densities, radii, out);
}